// round 9
// baseline (speedup 1.0000x reference)
#include <cuda_runtime.h>
#include <cuda_fp16.h>
#include <math.h>

typedef unsigned int u32;
typedef unsigned long long u64;

#define NSTEPS 511
#define Tt     512
#define NTHR   256
#define MROWS  128

// ---- smem byte offsets ----
#define SM_W1 0            // 16 tiles * 512B
#define SM_W2 8192         // 32 tiles
#define SM_W3 24576        // 48 tiles
#define SM_B1 49152        // f32[64]
#define SM_B2 49408        // f32[64]
#define SM_B3 49664        // f32[96] (permuted)
#define SM_KST 50048       // per-thread k-state: KSTRIDE floats each
#define KSTRIDE 100        // 5 stages * 16 floats + pad (100 % 32 == 4 -> LDS.128 conflict-free)
#define SMEM_BYTES (SM_KST + NTHR*KSTRIDE*4)   // 152,448 B

__constant__ float cA6[6][5] = {
    {0.f,0.f,0.f,0.f,0.f},
    {0.161f,0.f,0.f,0.f,0.f},
    {-0.008480655492356989f,0.335480655492357f,0.f,0.f,0.f},
    {2.8971530571054935f,-6.359448489975075f,4.3622954328695815f,0.f,0.f},
    {5.325864828439257f,-11.748883564062828f,7.4955393428898365f,-0.09249506636175525f,0.f},
    {5.86145544294642f,-12.92096931784711f,8.159367898576159f,-0.071584973281401f,-0.028269050394068383f}};
__constant__ float cBt[6] = {
    0.09646076681806523f,0.01f,0.4798896504144996f,
    1.379008574103742f,-3.290069515436081f,2.324710524099774f};

// ---- packed f32x2 helpers ----
__device__ __forceinline__ u64 pack2(float lo, float hi){
    u64 r; asm("mov.b64 %0, {%1, %2};" : "=l"(r) : "f"(lo), "f"(hi)); return r;
}
__device__ __forceinline__ void unpack2(u64 v, float& lo, float& hi){
    asm("mov.b64 {%0, %1}, %2;" : "=f"(lo), "=f"(hi) : "l"(v));
}
__device__ __forceinline__ u64 fma2(u64 a, u64 b, u64 c){
    u64 d; asm("fma.rn.f32x2 %0, %1, %2, %3;" : "=l"(d) : "l"(a), "l"(b), "l"(c)); return d;
}
__device__ __forceinline__ u64 d2l(double x){ return __double_as_longlong(x); }
__device__ __forceinline__ double l2d(u64 x){ return __longlong_as_double(x); }

// fast tanh: 1 - 2/(2^(x*2/ln2)+1). 2 MUFU + 3 fma-pipe ops.
__device__ __forceinline__ float ftanh(float x){
    float r;
    asm("{\n\t.reg .f32 e;\n\t"
        "mul.f32 e, %1, 0f4038AA3B;\n\t"
        "ex2.approx.f32 e, e;\n\t"
        "add.f32 e, e, 0f3F800000;\n\t"
        "rcp.approx.f32 e, e;\n\t"
        "fma.rn.f32 %0, e, 0fC0000000, 0f3F800000;\n\t"
        "}" : "=f"(r) : "f"(x));
    return r;
}

// packed hi/lo split: hi = f16x2(x,y), lo = f16x2 of residuals
__device__ __forceinline__ void split2(float x, float y, u32& hi, u32& lo){
    asm("cvt.rn.f16x2.f32 %0, %1, %2;" : "=r"(hi) : "f"(y), "f"(x));
    float hx, hy;
    asm("{\n\t.reg .f16 a,b;\n\tmov.b32 {a,b}, %2;\n\t"
        "cvt.f32.f16 %0, a;\n\tcvt.f32.f16 %1, b;\n\t}"
        : "=f"(hx), "=f"(hy) : "r"(hi));
    asm("cvt.rn.f16x2.f32 %0, %1, %2;" : "=r"(lo) : "f"(y-hy), "f"(x-hx));
}

// physical A-col p (0..31) -> logical h index
__device__ __forceinline__ int hphys(int p){
    return 8*((p&7)>>1) + 2*(p>>3) + (p&1);
}
// physical L3 out col p3 (0..95) -> logical w3 row (3h+c)
__device__ __forceinline__ int w3row(int p3){
    int j = p3>>3, r = p3&7, tg = r>>1, e = r&1;
    int q = 2*j + e, d = q/3, c = q%3;
    return 3*(8*tg + d) + c;
}

__device__ __forceinline__ void mma16816(float* c, const u32* a, u32 b0, u32 b1){
    asm("mma.sync.aligned.m16n8k16.row.col.f32.f16.f16.f32 "
        "{%0,%1,%2,%3}, {%4,%5,%6,%7}, {%8,%9}, {%0,%1,%2,%3};"
        : "+f"(c[0]), "+f"(c[1]), "+f"(c[2]), "+f"(c[3])
        : "r"(a[0]), "r"(a[1]), "r"(a[2]), "r"(a[3]), "r"(b0), "r"(b1));
}

template<int NJ, int NT>
__device__ __forceinline__ void runLayer(const u32* __restrict__ tiles,
                                         const float* __restrict__ bias,
                                         const u32 (*ah)[4], const u32 (*al)[4],
                                         float (*C)[4], int lane, int tg)
{
    #pragma unroll
    for (int j=0;j<NJ;++j){
        float2 bb = *(const float2*)(bias + 8*j + 2*tg);
        C[j][0]=bb.x; C[j][1]=bb.y; C[j][2]=bb.x; C[j][3]=bb.y;
    }
    #pragma unroll
    for (int t=0;t<NT;++t){
        uint4 w[NJ];
        #pragma unroll
        for (int j=0;j<NJ;++j)
            w[j] = *(const uint4*)(tiles + (j*NT+t)*128 + lane*4);
        #pragma unroll
        for (int j=0;j<NJ;++j) mma16816(C[j], ah[t], w[j].x, w[j].y);  // Ah*Bh
        #pragma unroll
        for (int j=0;j<NJ;++j) mma16816(C[j], al[t], w[j].x, w[j].y);  // Al*Bh
        #pragma unroll
        for (int j=0;j<NJ;++j) mma16816(C[j], ah[t], w[j].z, w[j].w);  // Ah*Bl
    }
}

// tanh + hi/lo split: C n-tile pair (2t,2t+1) -> A k-tile t
template<int NTo>
__device__ __forceinline__ void actSplit(const float (*C)[4], u32 (*ah)[4], u32 (*al)[4]){
    #pragma unroll
    for (int t=0;t<NTo;++t){
        split2(ftanh(C[2*t][0]),   ftanh(C[2*t][1]),   ah[t][0], al[t][0]);
        split2(ftanh(C[2*t][2]),   ftanh(C[2*t][3]),   ah[t][1], al[t][1]);
        split2(ftanh(C[2*t+1][0]), ftanh(C[2*t+1][1]), ah[t][2], al[t][2]);
        split2(ftanh(C[2*t+1][2]), ftanh(C[2*t+1][3]), ah[t][3], al[t][3]);
    }
}

__global__ void __launch_bounds__(NTHR, 1)
ncde_mma(const float* __restrict__ times, const float* __restrict__ grad,
         const float* __restrict__ w1, const float* __restrict__ pb1,
         const float* __restrict__ w2, const float* __restrict__ pb2,
         const float* __restrict__ w3, const float* __restrict__ pb3,
         const float* __restrict__ w_enc, const float* __restrict__ b_enc,
         const float* __restrict__ w_ro, const float* __restrict__ b_ro,
         float* __restrict__ out, int Bn)
{
    extern __shared__ float sm[];
    char* smc = (char*)sm;
    u32* tw1 = (u32*)(smc + SM_W1);
    u32* tw2 = (u32*)(smc + SM_W2);
    u32* tw3 = (u32*)(smc + SM_W3);
    float* b1s = (float*)(smc + SM_B1);
    float* b2s = (float*)(smc + SM_B2);
    float* b3s = (float*)(smc + SM_B3);

    const int tid = threadIdx.x, warp = tid>>5, lane = tid&31;
    const int g = lane>>2, tg = lane&3;
    float* kb = (float*)(smc + SM_KST) + tid*KSTRIDE;   // private k-state (k0..k4)

    // ---- build weight fragment tiles (hi/lo f16) ----
    for (int s = tid; s < 16*32; s += NTHR){
        int tile = s>>5, l = s&31;
        int j = tile>>1, t = tile&1;
        int gg = l>>2, tt = l&3;
        int n = 8*j+gg, k0 = 16*t+2*tt;
        float f0 = w1[n*32 + hphys(k0)],   f1 = w1[n*32 + hphys(k0+1)];
        float f8 = w1[n*32 + hphys(k0+8)], f9 = w1[n*32 + hphys(k0+9)];
        u32 h01,l01,h89,l89;
        split2(f0,f1,h01,l01); split2(f8,f9,h89,l89);
        u32* d = tw1 + tile*128 + l*4;
        d[0]=h01; d[1]=h89; d[2]=l01; d[3]=l89;
    }
    for (int s = tid; s < 32*32; s += NTHR){
        int tile = s>>5, l = s&31;
        int j = tile>>2, t = tile&3;
        int gg = l>>2, tt = l&3;
        int n = 8*j+gg, k0 = 16*t+2*tt;
        float f0 = w2[n*64+k0],   f1 = w2[n*64+k0+1];
        float f8 = w2[n*64+k0+8], f9 = w2[n*64+k0+9];
        u32 h01,l01,h89,l89;
        split2(f0,f1,h01,l01); split2(f8,f9,h89,l89);
        u32* d = tw2 + tile*128 + l*4;
        d[0]=h01; d[1]=h89; d[2]=l01; d[3]=l89;
    }
    for (int s = tid; s < 48*32; s += NTHR){
        int tile = s>>5, l = s&31;
        int j = tile>>2, t = tile&3;
        int gg = l>>2, tt = l&3;
        int n = 8*j+gg, k0 = 16*t+2*tt;
        int rr = w3row(n);
        float f0 = w3[rr*64+k0],   f1 = w3[rr*64+k0+1];
        float f8 = w3[rr*64+k0+8], f9 = w3[rr*64+k0+9];
        u32 h01,l01,h89,l89;
        split2(f0,f1,h01,l01); split2(f8,f9,h89,l89);
        u32* d = tw3 + tile*128 + l*4;
        d[0]=h01; d[1]=h89; d[2]=l01; d[3]=l89;
    }
    if (tid < 64) b1s[tid] = pb1[tid];
    if (tid < 64) b2s[tid] = pb2[tid];
    if (tid < 96) b3s[tid] = pb3[w3row(tid)];
    __syncthreads();

    // ---- per-thread state: rows g and g+8 of warp's 16-row block ----
    const int base = blockIdx.x*MROWS + warp*16;
    const int rowg = base + g, rowh = rowg + 8;
    const int rgc = (rowg < Bn) ? rowg : (Bn-1);
    const int rhc = (rowh < Bn) ? rowh : (Bn-1);
    const float dt = times[1] - times[0];
    const float* gA = grad + (size_t)rgc * (Tt*3);
    const float* gB = grad + (size_t)rhc * (Tt*3);

    // z state packed: zg2[j] = (z[2j], z[2j+1]) for row g; zh2 row h
    u64 zg2[4], zh2[4];
    #pragma unroll
    for (int j=0;j<4;++j){
        float v0 = w_enc[8*tg+2*j]   + b_enc[8*tg+2*j];
        float v1 = w_enc[8*tg+2*j+1] + b_enc[8*tg+2*j+1];
        zg2[j] = pack2(v0, v1);
        zh2[j] = pack2(v0, v1);
    }

    #pragma unroll 1
    for (int n=0; n<NSTEPS; ++n){
        float dqg[3], dqh[3];
        #pragma unroll
        for (int c=0;c<3;++c){ dqg[c] = gA[n*3+c]*dt; dqh[c] = gB[n*3+c]*dt; }

        #pragma unroll 1
        for (int sg=0; sg<6; ++sg){
            // ---- stage combine (packed): Y = z + sum_p A[sg][p] k_p ----
            u64 Yg2[4], Yh2[4];
            #pragma unroll
            for (int j=0;j<4;++j){ Yg2[j]=zg2[j]; Yh2[j]=zh2[j]; }
            for (int p=0;p<sg;++p){
                const float c = cA6[sg][p];
                const u64 cc = pack2(c, c);
                double2 ga = *(const double2*)(kb + p*16);
                double2 gb = *(const double2*)(kb + p*16 + 4);
                double2 ha = *(const double2*)(kb + p*16 + 8);
                double2 hb = *(const double2*)(kb + p*16 + 12);
                Yg2[0] = fma2(cc, d2l(ga.x), Yg2[0]);
                Yg2[1] = fma2(cc, d2l(ga.y), Yg2[1]);
                Yg2[2] = fma2(cc, d2l(gb.x), Yg2[2]);
                Yg2[3] = fma2(cc, d2l(gb.y), Yg2[3]);
                Yh2[0] = fma2(cc, d2l(ha.x), Yh2[0]);
                Yh2[1] = fma2(cc, d2l(ha.y), Yh2[1]);
                Yh2[2] = fma2(cc, d2l(hb.x), Yh2[2]);
                Yh2[3] = fma2(cc, d2l(hb.y), Yh2[3]);
            }
            u32 yah[2][4], yal[2][4];
            #pragma unroll
            for (int t=0;t<2;++t){
                float x, y;
                unpack2(Yg2[2*t],   x, y); split2(x, y, yah[t][0], yal[t][0]);
                unpack2(Yh2[2*t],   x, y); split2(x, y, yah[t][1], yal[t][1]);
                unpack2(Yg2[2*t+1], x, y); split2(x, y, yah[t][2], yal[t][2]);
                unpack2(Yh2[2*t+1], x, y); split2(x, y, yah[t][3], yal[t][3]);
            }

            // ---- L1 ----
            float C1[8][4];
            runLayer<8,2>(tw1, b1s, yah, yal, C1, lane, tg);
            u32 a2h[4][4], a2l[4][4];
            actSplit<4>(C1, a2h, a2l);

            // ---- L2 ----
            float C2[8][4];
            runLayer<8,4>(tw2, b2s, a2h, a2l, C2, lane, tg);
            u32 a3h[4][4], a3l[4][4];
            actSplit<4>(C2, a3h, a3l);

            // ---- L3 ----
            float C3[12][4];
            runLayer<12,4>(tw3, b3s, a3h, a3l, C3, lane, tg);

            // ---- dq contraction -> k ----
            float nkg[8], nkh[8];
            #pragma unroll
            for (int d=0;d<8;++d){ nkg[d]=0.f; nkh[d]=0.f; }
            #pragma unroll
            for (int j=0;j<12;++j){
                #pragma unroll
                for (int e=0;e<2;++e){
                    const int q = 2*j+e, d = q/3, c = q%3;
                    nkg[d] = fmaf(C3[j][e],   dqg[c], nkg[d]);
                    nkh[d] = fmaf(C3[j][2+e], dqh[c], nkh[d]);
                }
            }

            if (sg < 5){
                // store k_sg (vectorized, private)
                *(double2*)(kb + sg*16)      = make_double2(l2d(pack2(nkg[0],nkg[1])), l2d(pack2(nkg[2],nkg[3])));
                *(double2*)(kb + sg*16 + 4)  = make_double2(l2d(pack2(nkg[4],nkg[5])), l2d(pack2(nkg[6],nkg[7])));
                *(double2*)(kb + sg*16 + 8)  = make_double2(l2d(pack2(nkh[0],nkh[1])), l2d(pack2(nkh[2],nkh[3])));
                *(double2*)(kb + sg*16 + 12) = make_double2(l2d(pack2(nkh[4],nkh[5])), l2d(pack2(nkh[6],nkh[7])));
            } else {
                // ---- z += sum_p B[p] k_p  (k5 straight from registers) ----
                #pragma unroll
                for (int p=0;p<5;++p){
                    const u64 cc = pack2(cBt[p], cBt[p]);
                    double2 ga = *(const double2*)(kb + p*16);
                    double2 gb = *(const double2*)(kb + p*16 + 4);
                    double2 ha = *(const double2*)(kb + p*16 + 8);
                    double2 hb = *(const double2*)(kb + p*16 + 12);
                    zg2[0] = fma2(cc, d2l(ga.x), zg2[0]);
                    zg2[1] = fma2(cc, d2l(ga.y), zg2[1]);
                    zg2[2] = fma2(cc, d2l(gb.x), zg2[2]);
                    zg2[3] = fma2(cc, d2l(gb.y), zg2[3]);
                    zh2[0] = fma2(cc, d2l(ha.x), zh2[0]);
                    zh2[1] = fma2(cc, d2l(ha.y), zh2[1]);
                    zh2[2] = fma2(cc, d2l(hb.x), zh2[2]);
                    zh2[3] = fma2(cc, d2l(hb.y), zh2[3]);
                }
                const u64 c5 = pack2(cBt[5], cBt[5]);
                #pragma unroll
                for (int j=0;j<4;++j){
                    zg2[j] = fma2(c5, pack2(nkg[2*j], nkg[2*j+1]), zg2[j]);
                    zh2[j] = fma2(c5, pack2(nkh[2*j], nkh[2*j+1]), zh2[j]);
                }
            }
        }
    }

    // ---- readout ----
    float pg = 0.f, ph = 0.f;
    #pragma unroll
    for (int j=0;j<4;++j){
        float a, b;
        unpack2(zg2[j], a, b);
        pg = fmaf(a, w_ro[8*tg+2*j], pg);
        pg = fmaf(b, w_ro[8*tg+2*j+1], pg);
        unpack2(zh2[j], a, b);
        ph = fmaf(a, w_ro[8*tg+2*j], ph);
        ph = fmaf(b, w_ro[8*tg+2*j+1], ph);
    }
    pg += __shfl_xor_sync(0xffffffffu, pg, 1);
    pg += __shfl_xor_sync(0xffffffffu, pg, 2);
    ph += __shfl_xor_sync(0xffffffffu, ph, 1);
    ph += __shfl_xor_sync(0xffffffffu, ph, 2);
    if (tg == 0){
        const float br = b_ro[0];
        if (rowg < Bn) out[rowg] = 1.0f/(1.0f + expf(-(pg + br)));
        if (rowh < Bn) out[rowh] = 1.0f/(1.0f + expf(-(ph + br)));
    }
}

extern "C" void kernel_launch(void* const* d_in, const int* in_sizes, int n_in,
                              void* d_out, int out_size)
{
    const float* times=(const float*)d_in[0];
    const float* grad =(const float*)d_in[1];
    const float* w1=(const float*)d_in[2];  const float* b1=(const float*)d_in[3];
    const float* w2=(const float*)d_in[4];  const float* b2=(const float*)d_in[5];
    const float* w3=(const float*)d_in[6];  const float* b3=(const float*)d_in[7];
    const float* we=(const float*)d_in[8];  const float* be=(const float*)d_in[9];
    const float* wr=(const float*)d_in[10]; const float* br=(const float*)d_in[11];
    float* out=(float*)d_out;

    const int Bn = in_sizes[1] / (Tt*3);
    const int nblocks = (Bn + MROWS - 1) / MROWS;

    cudaFuncSetAttribute(ncde_mma, cudaFuncAttributeMaxDynamicSharedMemorySize,
                         (int)SMEM_BYTES);
    ncde_mma<<<nblocks, NTHR, SMEM_BYTES>>>(
        times, grad, w1, b1, w2, b2, w3, b3, we, be, wr, br, out, Bn);
}

// round 12
// speedup vs baseline: 1.5424x; 1.5424x over previous
#include <cuda_runtime.h>
#include <cuda_fp16.h>
#include <math.h>

typedef unsigned int u32;
typedef unsigned long long u64;

#define NSTEPS 511
#define Tt     512
#define NTHR   256
#define MROWS  128

// ---- smem byte offsets ----
#define SM_W1 0            // 16 tiles * 512B
#define SM_W2 8192         // 32 tiles
#define SM_W3 24576        // 48 tiles
#define SM_KST 49152       // packed k-state: u64[5 stages][8][NTHR]
#define SMEM_BYTES (SM_KST + 5*8*NTHR*8)   // 131,072 B

__constant__ float cA6[6][5] = {
    {0.f,0.f,0.f,0.f,0.f},
    {0.161f,0.f,0.f,0.f,0.f},
    {-0.008480655492356989f,0.335480655492357f,0.f,0.f,0.f},
    {2.8971530571054935f,-6.359448489975075f,4.3622954328695815f,0.f,0.f},
    {5.325864828439257f,-11.748883564062828f,7.4955393428898365f,-0.09249506636175525f,0.f},
    {5.86145544294642f,-12.92096931784711f,8.159367898576159f,-0.071584973281401f,-0.028269050394068383f}};
__constant__ float cBt[6] = {
    0.09646076681806523f,0.01f,0.4798896504144996f,
    1.379008574103742f,-3.290069515436081f,2.324710524099774f};

// ---- packed f32x2 helpers ----
__device__ __forceinline__ u64 pack2(float lo, float hi){
    u64 r; asm("mov.b64 %0, {%1, %2};" : "=l"(r) : "f"(lo), "f"(hi)); return r;
}
__device__ __forceinline__ void unpack2(u64 v, float& lo, float& hi){
    asm("mov.b64 {%0, %1}, %2;" : "=f"(lo), "=f"(hi) : "l"(v));
}
__device__ __forceinline__ u64 fma2(u64 a, u64 b, u64 c){
    u64 d; asm("fma.rn.f32x2 %0, %1, %2, %3;" : "=l"(d) : "l"(a), "l"(b), "l"(c)); return d;
}

// fast tanh: 1 - 2/(2^(x*2/ln2)+1). 2 MUFU + 3 fma-pipe ops, ~1e-6 err.
__device__ __forceinline__ float ftanh(float x){
    float r;
    asm("{\n\t.reg .f32 e;\n\t"
        "mul.f32 e, %1, 0f4038AA3B;\n\t"
        "ex2.approx.f32 e, e;\n\t"
        "add.f32 e, e, 0f3F800000;\n\t"
        "rcp.approx.f32 e, e;\n\t"
        "fma.rn.f32 %0, e, 0fC0000000, 0f3F800000;\n\t"
        "}" : "=f"(r) : "f"(x));
    return r;
}

// packed hi/lo split: hi = f16x2(x,y), lo = f16x2 of residuals
__device__ __forceinline__ void split2(float x, float y, u32& hi, u32& lo){
    asm("cvt.rn.f16x2.f32 %0, %1, %2;" : "=r"(hi) : "f"(y), "f"(x));
    float hx, hy;
    asm("{\n\t.reg .f16 a,b;\n\tmov.b32 {a,b}, %2;\n\t"
        "cvt.f32.f16 %0, a;\n\tcvt.f32.f16 %1, b;\n\t}"
        : "=f"(hx), "=f"(hy) : "r"(hi));
    asm("cvt.rn.f16x2.f32 %0, %1, %2;" : "=r"(lo) : "f"(y-hy), "f"(x-hx));
}

// physical A-col p (0..31) -> logical h index
__device__ __forceinline__ int hphys(int p){
    return 8*((p&7)>>1) + 2*(p>>3) + (p&1);
}
// physical L3 out col p3 (0..95) -> logical w3 row (3h+c)
__device__ __forceinline__ int w3row(int p3){
    int j = p3>>3, r = p3&7, tg = r>>1, e = r&1;
    int q = 2*j + e, d = q/3, c = q%3;
    return 3*(8*tg + d) + c;
}

__device__ __forceinline__ void mma16816(float* c, const u32* a, u32 b0, u32 b1){
    asm("mma.sync.aligned.m16n8k16.row.col.f32.f16.f16.f32 "
        "{%0,%1,%2,%3}, {%4,%5,%6,%7}, {%8,%9}, {%0,%1,%2,%3};"
        : "+f"(c[0]), "+f"(c[1]), "+f"(c[2]), "+f"(c[3])
        : "r"(a[0]), "r"(a[1]), "r"(a[2]), "r"(a[3]), "r"(b0), "r"(b1));
}

// 3-term split: Ah*Bh + Al*Bh + Ah*Bl. Biases come from registers.
template<int NJ, int NT>
__device__ __forceinline__ void runLayer(const u32* __restrict__ tiles,
                                         const float2* bias,
                                         const u32 (*ah)[4], const u32 (*al)[4],
                                         float (*C)[4], int lane)
{
    #pragma unroll
    for (int j=0;j<NJ;++j){
        C[j][0]=bias[j].x; C[j][1]=bias[j].y; C[j][2]=bias[j].x; C[j][3]=bias[j].y;
    }
    #pragma unroll
    for (int t=0;t<NT;++t){
        uint4 w[NJ];
        #pragma unroll
        for (int j=0;j<NJ;++j)
            w[j] = *(const uint4*)(tiles + (j*NT+t)*128 + lane*4);
        #pragma unroll
        for (int j=0;j<NJ;++j) mma16816(C[j], ah[t], w[j].x, w[j].y);  // Ah*Bh
        #pragma unroll
        for (int j=0;j<NJ;++j) mma16816(C[j], al[t], w[j].x, w[j].y);  // Al*Bh
        #pragma unroll
        for (int j=0;j<NJ;++j) mma16816(C[j], ah[t], w[j].z, w[j].w);  // Ah*Bl
    }
}

// tanh + hi/lo split: C n-tile pair (2t,2t+1) -> A k-tile t
template<int NTo>
__device__ __forceinline__ void actSplit(const float (*C)[4], u32 (*ah)[4], u32 (*al)[4]){
    #pragma unroll
    for (int t=0;t<NTo;++t){
        split2(ftanh(C[2*t][0]),   ftanh(C[2*t][1]),   ah[t][0], al[t][0]);
        split2(ftanh(C[2*t][2]),   ftanh(C[2*t][3]),   ah[t][1], al[t][1]);
        split2(ftanh(C[2*t+1][0]), ftanh(C[2*t+1][1]), ah[t][2], al[t][2]);
        split2(ftanh(C[2*t+1][2]), ftanh(C[2*t+1][3]), ah[t][3], al[t][3]);
    }
}

__global__ void __launch_bounds__(NTHR, 1)
ncde_mma(const float* __restrict__ times, const float* __restrict__ grad,
         const float* __restrict__ w1, const float* __restrict__ pb1,
         const float* __restrict__ w2, const float* __restrict__ pb2,
         const float* __restrict__ w3, const float* __restrict__ pb3,
         const float* __restrict__ w_enc, const float* __restrict__ b_enc,
         const float* __restrict__ w_ro, const float* __restrict__ b_ro,
         float* __restrict__ out, int Bn)
{
    extern __shared__ float sm[];
    char* smc = (char*)sm;
    u32* tw1 = (u32*)(smc + SM_W1);
    u32* tw2 = (u32*)(smc + SM_W2);
    u32* tw3 = (u32*)(smc + SM_W3);
    u64* kbuf = (u64*)(smc + SM_KST);   // [(p*8+j)*NTHR + tid]

    const int tid = threadIdx.x, warp = tid>>5, lane = tid&31;
    const int g = lane>>2, tg = lane&3;

    // ---- build weight fragment tiles (hi/lo f16) ----
    for (int s = tid; s < 16*32; s += NTHR){
        int tile = s>>5, l = s&31;
        int j = tile>>1, t = tile&1;
        int gg = l>>2, tt = l&3;
        int n = 8*j+gg, k0 = 16*t+2*tt;
        float f0 = w1[n*32 + hphys(k0)],   f1 = w1[n*32 + hphys(k0+1)];
        float f8 = w1[n*32 + hphys(k0+8)], f9 = w1[n*32 + hphys(k0+9)];
        u32 h01,l01,h89,l89;
        split2(f0,f1,h01,l01); split2(f8,f9,h89,l89);
        u32* d = tw1 + tile*128 + l*4;
        d[0]=h01; d[1]=h89; d[2]=l01; d[3]=l89;
    }
    for (int s = tid; s < 32*32; s += NTHR){
        int tile = s>>5, l = s&31;
        int j = tile>>2, t = tile&3;
        int gg = l>>2, tt = l&3;
        int n = 8*j+gg, k0 = 16*t+2*tt;
        float f0 = w2[n*64+k0],   f1 = w2[n*64+k0+1];
        float f8 = w2[n*64+k0+8], f9 = w2[n*64+k0+9];
        u32 h01,l01,h89,l89;
        split2(f0,f1,h01,l01); split2(f8,f9,h89,l89);
        u32* d = tw2 + tile*128 + l*4;
        d[0]=h01; d[1]=h89; d[2]=l01; d[3]=l89;
    }
    for (int s = tid; s < 48*32; s += NTHR){
        int tile = s>>5, l = s&31;
        int j = tile>>2, t = tile&3;
        int gg = l>>2, tt = l&3;
        int n = 8*j+gg, k0 = 16*t+2*tt;
        int rr = w3row(n);
        float f0 = w3[rr*64+k0],   f1 = w3[rr*64+k0+1];
        float f8 = w3[rr*64+k0+8], f9 = w3[rr*64+k0+9];
        u32 h01,l01,h89,l89;
        split2(f0,f1,h01,l01); split2(f8,f9,h89,l89);
        u32* d = tw3 + tile*128 + l*4;
        d[0]=h01; d[1]=h89; d[2]=l01; d[3]=l89;
    }
    __syncthreads();

    // ---- biases in registers (per-thread fragment slices) ----
    float2 b1f[8], b2f[8], b3f[12];
    #pragma unroll
    for (int j=0;j<8;++j){
        b1f[j] = make_float2(pb1[8*j+2*tg], pb1[8*j+2*tg+1]);
        b2f[j] = make_float2(pb2[8*j+2*tg], pb2[8*j+2*tg+1]);
    }
    #pragma unroll
    for (int j=0;j<12;++j)
        b3f[j] = make_float2(pb3[w3row(8*j+2*tg)], pb3[w3row(8*j+2*tg+1)]);

    // ---- per-thread state: rows g and g+8 of warp's 16-row block ----
    const int base = blockIdx.x*MROWS + warp*16;
    const int rowg = base + g, rowh = rowg + 8;
    const int rgc = (rowg < Bn) ? rowg : (Bn-1);
    const int rhc = (rowh < Bn) ? rowh : (Bn-1);
    const float dt = times[1] - times[0];
    const float* gA = grad + (size_t)rgc * (Tt*3);
    const float* gB = grad + (size_t)rhc * (Tt*3);

    // packed z state: zg2[j] = (z[2j], z[2j+1]) of this thread's 8 dims
    u64 zg2[4], zh2[4];
    #pragma unroll
    for (int j=0;j<4;++j){
        float v0 = w_enc[8*tg+2*j]   + b_enc[8*tg+2*j];
        float v1 = w_enc[8*tg+2*j+1] + b_enc[8*tg+2*j+1];
        zg2[j] = pack2(v0, v1);
        zh2[j] = pack2(v0, v1);
    }

    #pragma unroll 1
    for (int n=0; n<NSTEPS; ++n){
        float dqg[3], dqh[3];
        #pragma unroll
        for (int c=0;c<3;++c){ dqg[c] = gA[n*3+c]*dt; dqh[c] = gB[n*3+c]*dt; }

        #pragma unroll 1
        for (int sg=0; sg<6; ++sg){
            // ---- stage combine (packed): Y = z + sum_p A[sg][p] k_p ----
            u64 Yg2[4], Yh2[4];
            #pragma unroll
            for (int j=0;j<4;++j){ Yg2[j]=zg2[j]; Yh2[j]=zh2[j]; }
            for (int p=0;p<sg;++p){
                const float c = cA6[sg][p];
                const u64 cc = pack2(c, c);
                #pragma unroll
                for (int j=0;j<4;++j){
                    Yg2[j] = fma2(cc, kbuf[(p*8+j)*NTHR+tid],   Yg2[j]);
                    Yh2[j] = fma2(cc, kbuf[(p*8+4+j)*NTHR+tid], Yh2[j]);
                }
            }
            u32 yah[2][4], yal[2][4];
            #pragma unroll
            for (int t=0;t<2;++t){
                float x, y;
                unpack2(Yg2[2*t],   x, y); split2(x, y, yah[t][0], yal[t][0]);
                unpack2(Yh2[2*t],   x, y); split2(x, y, yah[t][1], yal[t][1]);
                unpack2(Yg2[2*t+1], x, y); split2(x, y, yah[t][2], yal[t][2]);
                unpack2(Yh2[2*t+1], x, y); split2(x, y, yah[t][3], yal[t][3]);
            }

            // ---- L1 ----
            float C1[8][4];
            runLayer<8,2>(tw1, b1f, yah, yal, C1, lane);
            u32 a2h[4][4], a2l[4][4];
            actSplit<4>(C1, a2h, a2l);

            // ---- L2 ----
            float C2[8][4];
            runLayer<8,4>(tw2, b2f, a2h, a2l, C2, lane);
            u32 a3h[4][4], a3l[4][4];
            actSplit<4>(C2, a3h, a3l);

            // ---- L3 ----
            float C3[12][4];
            runLayer<12,4>(tw3, b3f, a3h, a3l, C3, lane);

            // ---- dq contraction -> k ----
            float nkg[8], nkh[8];
            #pragma unroll
            for (int d=0;d<8;++d){ nkg[d]=0.f; nkh[d]=0.f; }
            #pragma unroll
            for (int j=0;j<12;++j){
                #pragma unroll
                for (int e=0;e<2;++e){
                    const int q = 2*j+e, d = q/3, c = q%3;
                    nkg[d] = fmaf(C3[j][e],   dqg[c], nkg[d]);
                    nkh[d] = fmaf(C3[j][2+e], dqh[c], nkh[d]);
                }
            }

            if (sg < 5){
                #pragma unroll
                for (int j=0;j<4;++j){
                    kbuf[(sg*8+j)*NTHR+tid]   = pack2(nkg[2*j], nkg[2*j+1]);
                    kbuf[(sg*8+4+j)*NTHR+tid] = pack2(nkh[2*j], nkh[2*j+1]);
                }
            } else {
                // ---- z += sum_p B[p] k_p (k5 straight from registers) ----
                #pragma unroll
                for (int p=0;p<5;++p){
                    const u64 cc = pack2(cBt[p], cBt[p]);
                    #pragma unroll
                    for (int j=0;j<4;++j){
                        zg2[j] = fma2(cc, kbuf[(p*8+j)*NTHR+tid],   zg2[j]);
                        zh2[j] = fma2(cc, kbuf[(p*8+4+j)*NTHR+tid], zh2[j]);
                    }
                }
                const u64 c5 = pack2(cBt[5], cBt[5]);
                #pragma unroll
                for (int j=0;j<4;++j){
                    zg2[j] = fma2(c5, pack2(nkg[2*j], nkg[2*j+1]), zg2[j]);
                    zh2[j] = fma2(c5, pack2(nkh[2*j], nkh[2*j+1]), zh2[j]);
                }
            }
        }
    }

    // ---- readout ----
    float pg = 0.f, ph = 0.f;
    #pragma unroll
    for (int j=0;j<4;++j){
        float a, b;
        unpack2(zg2[j], a, b);
        pg = fmaf(a, w_ro[8*tg+2*j], pg);
        pg = fmaf(b, w_ro[8*tg+2*j+1], pg);
        unpack2(zh2[j], a, b);
        ph = fmaf(a, w_ro[8*tg+2*j], ph);
        ph = fmaf(b, w_ro[8*tg+2*j+1], ph);
    }
    pg += __shfl_xor_sync(0xffffffffu, pg, 1);
    pg += __shfl_xor_sync(0xffffffffu, pg, 2);
    ph += __shfl_xor_sync(0xffffffffu, ph, 1);
    ph += __shfl_xor_sync(0xffffffffu, ph, 2);
    if (tg == 0){
        const float br = b_ro[0];
        if (rowg < Bn) out[rowg] = 1.0f/(1.0f + expf(-(pg + br)));
        if (rowh < Bn) out[rowh] = 1.0f/(1.0f + expf(-(ph + br)));
    }
}

extern "C" void kernel_launch(void* const* d_in, const int* in_sizes, int n_in,
                              void* d_out, int out_size)
{
    const float* times=(const float*)d_in[0];
    const float* grad =(const float*)d_in[1];
    const float* w1=(const float*)d_in[2];  const float* b1=(const float*)d_in[3];
    const float* w2=(const float*)d_in[4];  const float* b2=(const float*)d_in[5];
    const float* w3=(const float*)d_in[6];  const float* b3=(const float*)d_in[7];
    const float* we=(const float*)d_in[8];  const float* be=(const float*)d_in[9];
    const float* wr=(const float*)d_in[10]; const float* br=(const float*)d_in[11];
    float* out=(float*)d_out;

    const int Bn = in_sizes[1] / (Tt*3);
    const int nblocks = (Bn + MROWS - 1) / MROWS;

    cudaFuncSetAttribute(ncde_mma, cudaFuncAttributeMaxDynamicSharedMemorySize,
                         (int)SMEM_BYTES);
    ncde_mma<<<nblocks, NTHR, SMEM_BYTES>>>(
        times, grad, w1, b1, w2, b2, w3, b3, we, be, wr, br, out, Bn);
}